// round 8
// baseline (speedup 1.0000x reference)
#include <cuda_runtime.h>
#include <math.h>

// VectorQuantizer: N=65536 (64x32x32 BHWC-flat), C=64, K=1024.
// Output (float32): [quantized 4194304][vq_loss 1][indices 65536][perplexity 1]
// Numerics verified bit-exact in R1/R5/R7. Mainloop = R5/R7 (measured best),
// with cp.async double-buffered E staging (latency hidden, 1 barrier/chunk).

#define NPTS   65536
#define KC     1024
#define CD     64
#define HW     1024
#define MT     128
#define XSTRIDE 132
#define ESTRIDE 68

#define SM_XS   0
#define SM_ES0  (CD * XSTRIDE)            // 8448
#define SM_ES1  (SM_ES0 + 128 * ESTRIDE)  // +8704
#define SM_AS   (SM_ES1 + 128 * ESTRIDE)  // +8704
#define SMEM_FLOATS (SM_AS + 128)         // 25,984 floats = 103,936 B
#define SMEM_BYTES  (SMEM_FLOATS * 4)

#define OFF_LOSS  4194304
#define OFF_IDX   4194305
#define OFF_PERP  4259841

typedef unsigned long long u64;
typedef unsigned int u32;

__device__ float        g_esq[KC];
__device__ unsigned int g_hist[KC];
__device__ double       g_loss;

__device__ __forceinline__ u64 pack_dup(float x) {
    u64 r; asm("mov.b64 %0, {%1, %1};" : "=l"(r) : "f"(x)); return r;
}
__device__ __forceinline__ void unpack2(u64 v, float &lo, float &hi) {
    asm("mov.b64 {%0, %1}, %2;" : "=f"(lo), "=f"(hi) : "l"(v));
}
// packed fp32x2 FMA: each lane is IEEE-rn fp32 FMA (bit-identical to scalar FFMA)
__device__ __forceinline__ void ffma2(u64 &acc, u64 a, u64 b) {
    asm("fma.rn.f32x2 %0, %1, %2, %0;" : "+l"(acc) : "l"(a), "l"(b));
}
__device__ __forceinline__ u32 smem_u32(const void* p) {
    u32 a; asm("{ .reg .u64 t; cvta.to.shared.u64 t, %1; cvt.u32.u64 %0, t; }" : "=r"(a) : "l"(p));
    return a;
}
__device__ __forceinline__ void cp16(u32 dst, const void* src) {
    asm volatile("cp.async.cg.shared.global [%0], [%1], 16;" :: "r"(dst), "l"(src));
}
__device__ __forceinline__ void cp_commit() {
    asm volatile("cp.async.commit_group;" ::: "memory");
}
__device__ __forceinline__ void cp_wait0() {
    asm volatile("cp.async.wait_group 0;" ::: "memory");
}

// ---------------- init (split so vq_main is launch index 3 for ncu) ----------------
__global__ void vq_init_hist() {
    int t = blockIdx.x * blockDim.x + threadIdx.x;
    if (t < KC) g_hist[t] = 0u;
    if (t == 0) g_loss = 0.0;
}

// ---------------- esq ----------------
__global__ void vq_esq(const float* __restrict__ emb) {
    int k = blockIdx.x * blockDim.x + threadIdx.x;
    if (k < KC) {
        float s = 0.0f;
        const float* er = emb + (size_t)k * CD;
        #pragma unroll
        for (int c = 0; c < CD; ++c) {
            float e = er[c];
            s = __fadd_rn(s, __fmul_rn(e, e));
        }
        g_esq[k] = s;
    }
}

__global__ void vq_pad() {}

// ------- fused: distances + argmin + quantize + loss + hist -------
__global__ void __launch_bounds__(256) vq_main(const float* __restrict__ inputs,
                                               const float* __restrict__ emb,
                                               float* __restrict__ out) {
    extern __shared__ float sm[];
    float* xs  = sm + SM_XS;     // [CD][XSTRIDE]   xs[c*XSTRIDE + p]
    float* esb[2];
    esb[0] = sm + SM_ES0;        // [128][ESTRIDE] double-buffered E chunks
    esb[1] = sm + SM_ES1;
    float* as_ = sm + SM_AS;     // [128]; reused as idxs[] in the tail
    int*   idxs = (int*)as_;
    double* red = (double*)esb[0];  // tail block-reduce scratch (es dead then)

    const int t  = threadIdx.x;
    const int tr = t >> 4;    // 0..15 point group (8 pts each)
    const int tc = t & 15;    // 0..15 code lane
    const int n0 = blockIdx.x * MT;
    const int b  = n0 >> 10;
    const int p0 = n0 & 1023;
    const float* xbase = inputs + (size_t)b * (CD * HW) + p0;

    // per-thread staging geometry (8 float4s per chunk)
    u32 es_u32[2];
    es_u32[0] = smem_u32(esb[0]);
    es_u32[1] = smem_u32(esb[1]);

    // ---- kick off async stage of E chunk 0
    #pragma unroll
    for (int j = 0; j < 8; ++j) {
        int q  = t + j * 256;
        int kk = q >> 4;
        int cg = (q & 15) << 2;
        cp16(es_u32[0] + (u32)(kk * ESTRIDE + cg) * 4u,
             emb + (size_t)kk * CD + cg);
    }
    cp_commit();

    // ---- load x tile (transposed into [c][p])
    #pragma unroll
    for (int j = 0; j < 8; ++j) {
        int q  = t + j * 256;
        int c  = q >> 5;
        int i4 = (q & 31) << 2;
        float4 v = *reinterpret_cast<const float4*>(xbase + (size_t)c * HW + i4);
        *reinterpret_cast<float4*>(&xs[c * XSTRIDE + i4]) = v;
    }
    __syncthreads();

    // a = ||x||^2 : strictly sequential fp32
    if (t < MT) {
        float s = 0.0f;
        #pragma unroll
        for (int c = 0; c < CD; ++c) {
            float xv = xs[c * XSTRIDE + t];
            s = __fadd_rn(s, __fmul_rn(xv, xv));
        }
        as_[t] = s;
    }
    __syncthreads();

    float a_[8];
    #pragma unroll
    for (int i = 0; i < 8; ++i) a_[i] = as_[tr * 8 + i];

    float bestv[8];
    int   besti[8];
    #pragma unroll
    for (int i = 0; i < 8; ++i) { bestv[i] = __int_as_float(0x7f800000); besti[i] = 0x7fffffff; }

    #pragma unroll 1
    for (int kc = 0; kc < 8; ++kc) {
        cp_wait0();        // E chunk kc landed in esb[kc&1]
        __syncthreads();   // all warps: data visible; prior readers of esb[(kc+1)&1] done

        // async stage of chunk kc+1 into the other buffer (overlaps compute)
        if (kc + 1 < 8) {
            const float* src = emb + (size_t)(kc + 1) * 128 * CD;
            u32 dstb = es_u32[(kc + 1) & 1];
            #pragma unroll
            for (int j = 0; j < 8; ++j) {
                int q  = t + j * 256;
                int kk = q >> 4;
                int cg = (q & 15) << 2;
                cp16(dstb + (u32)(kk * ESTRIDE + cg) * 4u,
                     src + (size_t)kk * CD + cg);
            }
        }
        cp_commit();       // (empty group on last iter keeps wait0 cheap)

        const float* es = esb[kc & 1];

        u64 acc[8][4];
        #pragma unroll
        for (int j = 0; j < 8; ++j)
            #pragma unroll
            for (int i = 0; i < 4; ++i) acc[j][i] = 0ULL;

        #pragma unroll 4
        for (int c4 = 0; c4 < CD; c4 += 4) {
            float4 ef[8];
            #pragma unroll
            for (int j = 0; j < 8; ++j)
                ef[j] = *reinterpret_cast<const float4*>(&es[(j * 16 + tc) * ESTRIDE + c4]);
            #pragma unroll
            for (int cc = 0; cc < 4; ++cc) {
                const float* xr = &xs[(c4 + cc) * XSTRIDE + tr * 8];
                ulonglong2 Xa = *reinterpret_cast<const ulonglong2*>(xr);
                ulonglong2 Xb = *reinterpret_cast<const ulonglong2*>(xr + 4);
                #pragma unroll
                for (int j = 0; j < 8; ++j) {
                    float ev = (cc == 0) ? ef[j].x : (cc == 1) ? ef[j].y : (cc == 2) ? ef[j].z : ef[j].w;
                    u64 ed = pack_dup(ev);
                    ffma2(acc[j][0], ed, Xa.x);
                    ffma2(acc[j][1], ed, Xa.y);
                    ffma2(acc[j][2], ed, Xb.x);
                    ffma2(acc[j][3], ed, Xb.y);
                }
            }
        }

        // epilogue: d = (a - 2*dot) + esq; k strictly ascending per lane -> strict '<'
        #pragma unroll
        for (int j = 0; j < 8; ++j) {
            int k = kc * 128 + j * 16 + tc;
            float esq = __ldg(&g_esq[k]);
            #pragma unroll
            for (int i = 0; i < 4; ++i) {
                float d0, d1; unpack2(acc[j][i], d0, d1);
                int ii = i * 2;
                float dd0 = __fadd_rn(__fsub_rn(a_[ii],     __fmul_rn(2.0f, d0)), esq);
                float dd1 = __fadd_rn(__fsub_rn(a_[ii + 1], __fmul_rn(2.0f, d1)), esq);
                if (dd0 < bestv[ii])     { bestv[ii]     = dd0; besti[ii]     = k; }
                if (dd1 < bestv[ii + 1]) { bestv[ii + 1] = dd1; besti[ii + 1] = k; }
            }
        }
    }

    // cross-lane argmin over the 16 code lanes (first-index ties)
    #pragma unroll
    for (int off = 1; off < 16; off <<= 1) {
        #pragma unroll
        for (int i = 0; i < 8; ++i) {
            float ov = __shfl_xor_sync(0xffffffffu, bestv[i], off);
            int   oi = __shfl_xor_sync(0xffffffffu, besti[i], off);
            if (ov < bestv[i] || (ov == bestv[i] && oi < besti[i])) { bestv[i] = ov; besti[i] = oi; }
        }
    }
    if (tc == 0) {
        #pragma unroll
        for (int i = 0; i < 8; ++i) {
            int p = tr * 8 + i;
            idxs[p] = besti[i];
            out[OFF_IDX + n0 + p] = (float)besti[i];
            atomicAdd(&g_hist[besti[i]], 1u);
        }
    }
    __syncthreads();   // idxs visible; mainloop smem readers done

    // ---- fused quantize + straight-through + loss (xs still resident) ----
    {
        const int p = t >> 1;
        const int h = t & 1;
        const int c0 = 32 * h;
        const int k = idxs[p];
        const float* eb = emb + (size_t)k * CD + c0;
        float* ob = out + (size_t)(n0 + p) * CD + c0;
        const float* xcol = xs + c0 * XSTRIDE + p;

        double s = 0.0;
        #pragma unroll
        for (int j = 0; j < 8; ++j) {
            float4 qv = __ldg(reinterpret_cast<const float4*>(eb) + j);
            float x0 = xcol[(4 * j + 0) * XSTRIDE];
            float x1 = xcol[(4 * j + 1) * XSTRIDE];
            float x2 = xcol[(4 * j + 2) * XSTRIDE];
            float x3 = xcol[(4 * j + 3) * XSTRIDE];
            float e0 = __fsub_rn(qv.x, x0);
            float e1 = __fsub_rn(qv.y, x1);
            float e2 = __fsub_rn(qv.z, x2);
            float e3 = __fsub_rn(qv.w, x3);
            float4 o;  // straight-through: x + (q - x)
            o.x = __fadd_rn(x0, e0);
            o.y = __fadd_rn(x1, e1);
            o.z = __fadd_rn(x2, e2);
            o.w = __fadd_rn(x3, e3);
            *reinterpret_cast<float4*>(ob + 4 * j) = o;
            s += (double)__fmul_rn(e0, e0) + (double)__fmul_rn(e1, e1)
               + (double)__fmul_rn(e2, e2) + (double)__fmul_rn(e3, e3);
        }
        #pragma unroll
        for (int off = 16; off > 0; off >>= 1)
            s += __shfl_down_sync(0xffffffffu, s, off);
        if ((t & 31) == 0) red[t >> 5] = s;
        __syncthreads();
        if (t == 0) {
            double tot = 0.0;
            #pragma unroll
            for (int w = 0; w < 8; ++w) tot += red[w];
            atomicAdd(&g_loss, tot);
        }
    }
}

// ---------------- finalize ----------------
__global__ void vq_final(float* __restrict__ out) {
    __shared__ double red[256];
    int t = threadIdx.x;
    double s = 0.0;
    for (int k = t; k < KC; k += 256) {
        float cnt = (float)g_hist[k];
        float pr  = __fmul_rn(cnt, 1.0f / 65536.0f);
        float lg  = logf(__fadd_rn(pr, 1e-10f));
        s += (double)__fmul_rn(pr, lg);
    }
    red[t] = s;
    __syncthreads();
    for (int off = 128; off > 0; off >>= 1) {
        if (t < off) red[t] += red[t + off];
        __syncthreads();
    }
    if (t == 0) {
        float m = (float)(g_loss / 4194304.0);
        out[OFF_LOSS] = __fadd_rn(m, __fmul_rn(0.25f, m));
        out[OFF_PERP] = expf(-(float)red[0]);
    }
}

extern "C" void kernel_launch(void* const* d_in, const int* in_sizes, int n_in,
                              void* d_out, int out_size) {
    const float* inputs = (const float*)d_in[0];
    const float* emb    = (const float*)d_in[1];
    if (n_in >= 2 && in_sizes[0] == KC * CD && in_sizes[1] == NPTS * CD) {
        const float* tmp = inputs; inputs = emb; emb = tmp;
    }
    float* out = (float*)d_out;

    cudaFuncSetAttribute(vq_main, cudaFuncAttributeMaxDynamicSharedMemorySize, SMEM_BYTES);

    // launch order arranged so vq_main is launch index 3 (ncu captures idx 3)
    vq_init_hist<<<1, 1024>>>();
    vq_esq<<<KC / 256, 256>>>(emb);
    vq_pad<<<1, 32>>>();
    vq_main<<<NPTS / MT, 256, SMEM_BYTES>>>(inputs, emb, out);
    vq_final<<<1, 256>>>(out);
}

// round 9
// speedup vs baseline: 1.0348x; 1.0348x over previous
#include <cuda_runtime.h>
#include <math.h>

// VectorQuantizer: N=65536 (64x32x32 BHWC-flat), C=64, K=1024.
// Output (float32): [quantized 4194304][vq_loss 1][indices 65536][perplexity 1]
// Numerics verified bit-exact R1/R5/R7. R9: P8xQ4 tile -> ~100 regs ->
// 2 blocks/SM (was 176 regs / 1 block), cp.async double-buffered 64-code chunks.

#define NPTS   65536
#define KC     1024
#define CD     64
#define HW     1024
#define MT     128
#define KCH    64
#define NCH    (KC / KCH)     // 16 chunks
#define XSTRIDE 132
#define ESTRIDE 68

#define SM_XS   0
#define SM_ES0  (CD * XSTRIDE)            // 8448
#define SM_ES1  (SM_ES0 + KCH * ESTRIDE)  // +4352
#define SM_AS   (SM_ES1 + KCH * ESTRIDE)  // +4352
#define SMEM_FLOATS (SM_AS + 128)         // 17,280 floats = 69,120 B -> 2 blocks/SM
#define SMEM_BYTES  (SMEM_FLOATS * 4)

#define OFF_LOSS  4194304
#define OFF_IDX   4194305
#define OFF_PERP  4259841

typedef unsigned long long u64;
typedef unsigned int u32;

__device__ float        g_esq[KC];
__device__ unsigned int g_hist[KC];
__device__ double       g_loss;

__device__ __forceinline__ u64 pack_dup(float x) {
    u64 r; asm("mov.b64 %0, {%1, %1};" : "=l"(r) : "f"(x)); return r;
}
__device__ __forceinline__ void unpack2(u64 v, float &lo, float &hi) {
    asm("mov.b64 {%0, %1}, %2;" : "=f"(lo), "=f"(hi) : "l"(v));
}
// packed fp32x2 FMA: each lane is IEEE-rn fp32 FMA (bit-identical to scalar FFMA)
__device__ __forceinline__ void ffma2(u64 &acc, u64 a, u64 b) {
    asm("fma.rn.f32x2 %0, %1, %2, %0;" : "+l"(acc) : "l"(a), "l"(b));
}
__device__ __forceinline__ u32 smem_u32(const void* p) {
    u32 a; asm("{ .reg .u64 t; cvta.to.shared.u64 t, %1; cvt.u32.u64 %0, t; }" : "=r"(a) : "l"(p));
    return a;
}
__device__ __forceinline__ void cp16(u32 dst, const void* src) {
    asm volatile("cp.async.cg.shared.global [%0], [%1], 16;" :: "r"(dst), "l"(src));
}
__device__ __forceinline__ void cp_commit() {
    asm volatile("cp.async.commit_group;" ::: "memory");
}
__device__ __forceinline__ void cp_wait0() {
    asm volatile("cp.async.wait_group 0;" ::: "memory");
}

// ---------------- init ----------------
__global__ void vq_init_hist() {
    int t = blockIdx.x * blockDim.x + threadIdx.x;
    if (t < KC) g_hist[t] = 0u;
    if (t == 0) g_loss = 0.0;
}

// ---------------- esq ----------------
__global__ void vq_esq(const float* __restrict__ emb) {
    int k = blockIdx.x * blockDim.x + threadIdx.x;
    if (k < KC) {
        float s = 0.0f;
        const float* er = emb + (size_t)k * CD;
        #pragma unroll
        for (int c = 0; c < CD; ++c) {
            float e = er[c];
            s = __fadd_rn(s, __fmul_rn(e, e));
        }
        g_esq[k] = s;
    }
}

__global__ void vq_pad() {}

// ------- fused: distances + argmin + quantize + loss + hist -------
__global__ void __launch_bounds__(256, 2) vq_main(const float* __restrict__ inputs,
                                                  const float* __restrict__ emb,
                                                  float* __restrict__ out) {
    extern __shared__ float sm[];
    float* xs  = sm + SM_XS;     // [CD][XSTRIDE]   xs[c*XSTRIDE + p]
    float* as_ = sm + SM_AS;     // [128]; reused as idxs[] in tail
    int*   idxs = (int*)as_;
    double* red = (double*)(sm + SM_ES0);  // tail scratch (es dead then)

    const int t  = threadIdx.x;
    const int tr = t >> 4;    // 0..15 point group (8 pts each)
    const int tc = t & 15;    // 0..15 code lane (4 codes each: j*16+tc)
    const int n0 = blockIdx.x * MT;
    const int b  = n0 >> 10;
    const int p0 = n0 & 1023;
    const float* xbase = inputs + (size_t)b * (CD * HW) + p0;

    u32 es_u32[2];
    es_u32[0] = smem_u32(sm + SM_ES0);
    es_u32[1] = smem_u32(sm + SM_ES1);
    const float* esf[2] = { sm + SM_ES0, sm + SM_ES1 };

    // per-thread staging slot (4 float4s per 64-code chunk)
    // q = t + 256j -> code kk = q>>4 (0..63), channel group cg = (q&15)*4
    // kick off async stage of E chunk 0
    #pragma unroll
    for (int j = 0; j < 4; ++j) {
        int q  = t + j * 256;
        int kk = q >> 4;
        int cg = (q & 15) << 2;
        cp16(es_u32[0] + (u32)(kk * ESTRIDE + cg) * 4u, emb + (size_t)kk * CD + cg);
    }
    cp_commit();

    // ---- load x tile (transposed into [c][p])
    #pragma unroll
    for (int j = 0; j < 8; ++j) {
        int q  = t + j * 256;
        int c  = q >> 5;
        int i4 = (q & 31) << 2;
        float4 v = *reinterpret_cast<const float4*>(xbase + (size_t)c * HW + i4);
        *reinterpret_cast<float4*>(&xs[c * XSTRIDE + i4]) = v;
    }
    __syncthreads();

    // a = ||x||^2 : strictly sequential fp32
    if (t < MT) {
        float s = 0.0f;
        #pragma unroll
        for (int c = 0; c < CD; ++c) {
            float xv = xs[c * XSTRIDE + t];
            s = __fadd_rn(s, __fmul_rn(xv, xv));
        }
        as_[t] = s;
    }
    __syncthreads();

    float a_[8];
    #pragma unroll
    for (int i = 0; i < 8; ++i) a_[i] = as_[tr * 8 + i];

    float bestv[8];
    int   besti[8];
    #pragma unroll
    for (int i = 0; i < 8; ++i) { bestv[i] = __int_as_float(0x7f800000); besti[i] = 0x7fffffff; }

    #pragma unroll 1
    for (int kc = 0; kc < NCH; ++kc) {
        cp_wait0();        // chunk kc landed in buffer kc&1
        __syncthreads();   // visible to all; prior readers of other buffer done

        // stage chunk kc+1 (overlaps compute)
        if (kc + 1 < NCH) {
            const float* src = emb + (size_t)(kc + 1) * KCH * CD;
            u32 dstb = es_u32[(kc + 1) & 1];
            #pragma unroll
            for (int j = 0; j < 4; ++j) {
                int q  = t + j * 256;
                int kk = q >> 4;
                int cg = (q & 15) << 2;
                cp16(dstb + (u32)(kk * ESTRIDE + cg) * 4u, src + (size_t)kk * CD + cg);
            }
        }
        cp_commit();

        const float* es = esf[kc & 1];

        u64 acc[4][4];     // [code j][point pair i]
        #pragma unroll
        for (int j = 0; j < 4; ++j)
            #pragma unroll
            for (int i = 0; i < 4; ++i) acc[j][i] = 0ULL;

        #pragma unroll 4
        for (int c4 = 0; c4 < CD; c4 += 4) {
            float4 ef[4];
            #pragma unroll
            for (int j = 0; j < 4; ++j)
                ef[j] = *reinterpret_cast<const float4*>(&es[(j * 16 + tc) * ESTRIDE + c4]);
            #pragma unroll
            for (int cc = 0; cc < 4; ++cc) {
                const float* xr = &xs[(c4 + cc) * XSTRIDE + tr * 8];
                ulonglong2 Xa = *reinterpret_cast<const ulonglong2*>(xr);
                ulonglong2 Xb = *reinterpret_cast<const ulonglong2*>(xr + 4);
                #pragma unroll
                for (int j = 0; j < 4; ++j) {
                    float ev = (cc == 0) ? ef[j].x : (cc == 1) ? ef[j].y : (cc == 2) ? ef[j].z : ef[j].w;
                    u64 ed = pack_dup(ev);
                    ffma2(acc[j][0], ed, Xa.x);
                    ffma2(acc[j][1], ed, Xa.y);
                    ffma2(acc[j][2], ed, Xb.x);
                    ffma2(acc[j][3], ed, Xb.y);
                }
            }
        }

        // epilogue: d = (a - 2*dot) + esq; k ascending per lane -> strict '<'
        #pragma unroll
        for (int j = 0; j < 4; ++j) {
            int k = kc * KCH + j * 16 + tc;
            float esq = __ldg(&g_esq[k]);
            #pragma unroll
            for (int i = 0; i < 4; ++i) {
                float d0, d1; unpack2(acc[j][i], d0, d1);
                int ii = i * 2;
                float dd0 = __fadd_rn(__fsub_rn(a_[ii],     __fmul_rn(2.0f, d0)), esq);
                float dd1 = __fadd_rn(__fsub_rn(a_[ii + 1], __fmul_rn(2.0f, d1)), esq);
                if (dd0 < bestv[ii])     { bestv[ii]     = dd0; besti[ii]     = k; }
                if (dd1 < bestv[ii + 1]) { bestv[ii + 1] = dd1; besti[ii + 1] = k; }
            }
        }
    }

    // cross-lane argmin over the 16 code lanes (first-index ties)
    #pragma unroll
    for (int off = 1; off < 16; off <<= 1) {
        #pragma unroll
        for (int i = 0; i < 8; ++i) {
            float ov = __shfl_xor_sync(0xffffffffu, bestv[i], off);
            int   oi = __shfl_xor_sync(0xffffffffu, besti[i], off);
            if (ov < bestv[i] || (ov == bestv[i] && oi < besti[i])) { bestv[i] = ov; besti[i] = oi; }
        }
    }
    if (tc == 0) {
        #pragma unroll
        for (int i = 0; i < 8; ++i) {
            int p = tr * 8 + i;
            idxs[p] = besti[i];
            out[OFF_IDX + n0 + p] = (float)besti[i];
            atomicAdd(&g_hist[besti[i]], 1u);
        }
    }
    __syncthreads();   // idxs visible; mainloop smem readers done

    // ---- fused quantize + straight-through + loss (xs still resident) ----
    {
        const int p = t >> 1;
        const int h = t & 1;
        const int c0 = 32 * h;
        const int k = idxs[p];
        const float* eb = emb + (size_t)k * CD + c0;
        float* ob = out + (size_t)(n0 + p) * CD + c0;
        const float* xcol = xs + c0 * XSTRIDE + p;

        double s = 0.0;
        #pragma unroll
        for (int j = 0; j < 8; ++j) {
            float4 qv = __ldg(reinterpret_cast<const float4*>(eb) + j);
            float x0 = xcol[(4 * j + 0) * XSTRIDE];
            float x1 = xcol[(4 * j + 1) * XSTRIDE];
            float x2 = xcol[(4 * j + 2) * XSTRIDE];
            float x3 = xcol[(4 * j + 3) * XSTRIDE];
            float e0 = __fsub_rn(qv.x, x0);
            float e1 = __fsub_rn(qv.y, x1);
            float e2 = __fsub_rn(qv.z, x2);
            float e3 = __fsub_rn(qv.w, x3);
            float4 o;  // straight-through: x + (q - x)
            o.x = __fadd_rn(x0, e0);
            o.y = __fadd_rn(x1, e1);
            o.z = __fadd_rn(x2, e2);
            o.w = __fadd_rn(x3, e3);
            *reinterpret_cast<float4*>(ob + 4 * j) = o;
            s += (double)__fmul_rn(e0, e0) + (double)__fmul_rn(e1, e1)
               + (double)__fmul_rn(e2, e2) + (double)__fmul_rn(e3, e3);
        }
        #pragma unroll
        for (int off = 16; off > 0; off >>= 1)
            s += __shfl_down_sync(0xffffffffu, s, off);
        if ((t & 31) == 0) red[t >> 5] = s;
        __syncthreads();
        if (t == 0) {
            double tot = 0.0;
            #pragma unroll
            for (int w = 0; w < 8; ++w) tot += red[w];
            atomicAdd(&g_loss, tot);
        }
    }
}

// ---------------- finalize ----------------
__global__ void vq_final(float* __restrict__ out) {
    __shared__ double red[256];
    int t = threadIdx.x;
    double s = 0.0;
    for (int k = t; k < KC; k += 256) {
        float cnt = (float)g_hist[k];
        float pr  = __fmul_rn(cnt, 1.0f / 65536.0f);
        float lg  = logf(__fadd_rn(pr, 1e-10f));
        s += (double)__fmul_rn(pr, lg);
    }
    red[t] = s;
    __syncthreads();
    for (int off = 128; off > 0; off >>= 1) {
        if (t < off) red[t] += red[t + off];
        __syncthreads();
    }
    if (t == 0) {
        float m = (float)(g_loss / 4194304.0);
        out[OFF_LOSS] = __fadd_rn(m, __fmul_rn(0.25f, m));
        out[OFF_PERP] = expf(-(float)red[0]);
    }
}

extern "C" void kernel_launch(void* const* d_in, const int* in_sizes, int n_in,
                              void* d_out, int out_size) {
    const float* inputs = (const float*)d_in[0];
    const float* emb    = (const float*)d_in[1];
    if (n_in >= 2 && in_sizes[0] == KC * CD && in_sizes[1] == NPTS * CD) {
        const float* tmp = inputs; inputs = emb; emb = tmp;
    }
    float* out = (float*)d_out;

    cudaFuncSetAttribute(vq_main, cudaFuncAttributeMaxDynamicSharedMemorySize, SMEM_BYTES);

    // launch order keeps vq_main at launch index 3 (ncu captures idx 3)
    vq_init_hist<<<1, 1024>>>();
    vq_esq<<<KC / 256, 256>>>(emb);
    vq_pad<<<1, 32>>>();
    vq_main<<<NPTS / MT, 256, SMEM_BYTES>>>(inputs, emb, out);
    vq_final<<<1, 256>>>(out);
}

// round 10
// speedup vs baseline: 1.1088x; 1.0715x over previous
#include <cuda_runtime.h>
#include <math.h>

// VectorQuantizer: N=65536 (64x32x32 BHWC-flat), C=64, K=1024.
// Output (float32): [quantized 4194304][vq_loss 1][indices 65536][perplexity 1]
// Numerics verified bit-exact R1/R5/R7/R9. R10 = R9 (P8xQ4, cp.async dbuf,
// 2 blocks/SM) with register demand trimmed below the 128 cap (no spills).

#define NPTS   65536
#define KC     1024
#define CD     64
#define HW     1024
#define MT     128
#define KCH    64
#define NCH    (KC / KCH)     // 16 chunks
#define XSTRIDE 132
#define ESTRIDE 68
#define ESBUF   (KCH * ESTRIDE)          // 4352 floats per buffer

#define SM_XS   0
#define SM_ES0  (CD * XSTRIDE)           // 8448
#define SM_AS   (SM_ES0 + 2 * ESBUF)     // 8448+8704 = 17152
#define SM_IDX  (SM_AS + 128)
#define SMEM_FLOATS (SM_IDX + 128)       // 17408 floats = 69,632 B -> 2 blocks/SM
#define SMEM_BYTES  (SMEM_FLOATS * 4)

#define OFF_LOSS  4194304
#define OFF_IDX   4194305
#define OFF_PERP  4259841

typedef unsigned long long u64;
typedef unsigned int u32;

__device__ float        g_esq[KC];
__device__ unsigned int g_hist[KC];
__device__ double       g_loss;

__device__ __forceinline__ u64 pack_dup(float x) {
    u64 r; asm("mov.b64 %0, {%1, %1};" : "=l"(r) : "f"(x)); return r;
}
__device__ __forceinline__ void unpack2(u64 v, float &lo, float &hi) {
    asm("mov.b64 {%0, %1}, %2;" : "=f"(lo), "=f"(hi) : "l"(v));
}
// packed fp32x2 FMA: each lane is IEEE-rn fp32 FMA (bit-identical to scalar FFMA)
__device__ __forceinline__ void ffma2(u64 &acc, u64 a, u64 b) {
    asm("fma.rn.f32x2 %0, %1, %2, %0;" : "+l"(acc) : "l"(a), "l"(b));
}
__device__ __forceinline__ u32 smem_u32(const void* p) {
    u32 a; asm("{ .reg .u64 t; cvta.to.shared.u64 t, %1; cvt.u32.u64 %0, t; }" : "=r"(a) : "l"(p));
    return a;
}
__device__ __forceinline__ void cp16(u32 dst, const void* src) {
    asm volatile("cp.async.cg.shared.global [%0], [%1], 16;" :: "r"(dst), "l"(src));
}
__device__ __forceinline__ void cp_commit() {
    asm volatile("cp.async.commit_group;" ::: "memory");
}
__device__ __forceinline__ void cp_wait0() {
    asm volatile("cp.async.wait_group 0;" ::: "memory");
}

// ---------------- init ----------------
__global__ void vq_init_hist() {
    int t = blockIdx.x * blockDim.x + threadIdx.x;
    if (t < KC) g_hist[t] = 0u;
    if (t == 0) g_loss = 0.0;
}

// ---------------- esq ----------------
__global__ void vq_esq(const float* __restrict__ emb) {
    int k = blockIdx.x * blockDim.x + threadIdx.x;
    if (k < KC) {
        float s = 0.0f;
        const float* er = emb + (size_t)k * CD;
        #pragma unroll
        for (int c = 0; c < CD; ++c) {
            float e = er[c];
            s = __fadd_rn(s, __fmul_rn(e, e));
        }
        g_esq[k] = s;
    }
}

__global__ void vq_pad() {}

// ------- fused: distances + argmin + quantize + loss + hist -------
__global__ void __launch_bounds__(256, 2) vq_main(const float* __restrict__ inputs,
                                                  const float* __restrict__ emb,
                                                  float* __restrict__ out) {
    extern __shared__ float sm[];
    float* xs   = sm + SM_XS;    // [CD][XSTRIDE]  xs[c*XSTRIDE + p]
    float* as_  = sm + SM_AS;    // [128] ||x||^2 (kept live for epilogues)
    int*   idxs = (int*)(sm + SM_IDX);
    double* red = (double*)(sm + SM_ES0);  // tail scratch (es dead then)

    const int t  = threadIdx.x;
    const int tr = t >> 4;    // 0..15 point group (8 pts each)
    const int tc = t & 15;    // 0..15 code lane (4 codes: j*16+tc)
    const int n0 = blockIdx.x * MT;
    const int b  = n0 >> 10;
    const int p0 = n0 & 1023;
    const float* xbase = inputs + (size_t)b * (CD * HW) + p0;

    // single es base; buffer b at byte offset b*ESBUF*4
    const u32 es_base = smem_u32(sm + SM_ES0);
    // this thread's staging slot offsets (code kk = q>>4, cgroup cg = (q&15)*4)
    const int skk = t >> 4;          // base code for j=0 (q=t)
    const int scg = (t & 15) << 2;

    // kick off async stage of E chunk 0 into buffer 0
    #pragma unroll
    for (int j = 0; j < 4; ++j) {
        int kk = skk + j * 16;
        cp16(es_base + (u32)(kk * ESTRIDE + scg) * 4u, emb + (size_t)kk * CD + scg);
    }
    cp_commit();

    // ---- load x tile (transposed into [c][p])
    #pragma unroll
    for (int j = 0; j < 8; ++j) {
        int q  = t + j * 256;
        int c  = q >> 5;
        int i4 = (q & 31) << 2;
        float4 v = *reinterpret_cast<const float4*>(xbase + (size_t)c * HW + i4);
        *reinterpret_cast<float4*>(&xs[c * XSTRIDE + i4]) = v;
    }
    __syncthreads();

    // a = ||x||^2 : strictly sequential fp32
    if (t < MT) {
        float s = 0.0f;
        #pragma unroll
        for (int c = 0; c < CD; ++c) {
            float xv = xs[c * XSTRIDE + t];
            s = __fadd_rn(s, __fmul_rn(xv, xv));
        }
        as_[t] = s;
    }
    __syncthreads();

    float bestv[8];
    int   besti[8];
    #pragma unroll
    for (int i = 0; i < 8; ++i) { bestv[i] = __int_as_float(0x7f800000); besti[i] = 0x7fffffff; }

    #pragma unroll 1
    for (int kc = 0; kc < NCH; ++kc) {
        cp_wait0();        // chunk kc landed in buffer kc&1
        __syncthreads();   // visible; prior readers of other buffer done

        // stage chunk kc+1 into the other buffer (overlaps compute)
        if (kc + 1 < NCH) {
            const float* src = emb + (size_t)(kc + 1) * KCH * CD + scg;
            u32 dstb = es_base + (u32)(((kc + 1) & 1) * ESBUF + scg) * 4u;
            #pragma unroll
            for (int j = 0; j < 4; ++j) {
                int kk = skk + j * 16;
                cp16(dstb + (u32)(kk * ESTRIDE) * 4u, src + (size_t)kk * CD);
            }
        }
        cp_commit();

        const float* es = sm + SM_ES0 + (kc & 1) * ESBUF;

        u64 acc[4][4];     // [code j][point pair i]
        #pragma unroll
        for (int j = 0; j < 4; ++j)
            #pragma unroll
            for (int i = 0; i < 4; ++i) acc[j][i] = 0ULL;

        #pragma unroll 4
        for (int c4 = 0; c4 < CD; c4 += 4) {
            float4 ef[4];
            #pragma unroll
            for (int j = 0; j < 4; ++j)
                ef[j] = *reinterpret_cast<const float4*>(&es[(j * 16 + tc) * ESTRIDE + c4]);
            #pragma unroll
            for (int cc = 0; cc < 4; ++cc) {
                const float* xr = &xs[(c4 + cc) * XSTRIDE + tr * 8];
                ulonglong2 Xa = *reinterpret_cast<const ulonglong2*>(xr);
                ulonglong2 Xb = *reinterpret_cast<const ulonglong2*>(xr + 4);
                #pragma unroll
                for (int j = 0; j < 4; ++j) {
                    float ev = (cc == 0) ? ef[j].x : (cc == 1) ? ef[j].y : (cc == 2) ? ef[j].z : ef[j].w;
                    u64 ed = pack_dup(ev);
                    ffma2(acc[j][0], ed, Xa.x);
                    ffma2(acc[j][1], ed, Xa.y);
                    ffma2(acc[j][2], ed, Xb.x);
                    ffma2(acc[j][3], ed, Xb.y);
                }
            }
        }

        // epilogue: d = (a - 2*dot) + esq; a reloaded from smem (saves 8 live regs)
        #pragma unroll
        for (int j = 0; j < 4; ++j) {
            int k = kc * KCH + j * 16 + tc;
            float esq = __ldg(&g_esq[k]);
            #pragma unroll
            for (int i = 0; i < 4; ++i) {
                float d0, d1; unpack2(acc[j][i], d0, d1);
                int ii = i * 2;
                float a0 = as_[tr * 8 + ii];
                float a1 = as_[tr * 8 + ii + 1];
                float dd0 = __fadd_rn(__fsub_rn(a0, __fmul_rn(2.0f, d0)), esq);
                float dd1 = __fadd_rn(__fsub_rn(a1, __fmul_rn(2.0f, d1)), esq);
                if (dd0 < bestv[ii])     { bestv[ii]     = dd0; besti[ii]     = k; }
                if (dd1 < bestv[ii + 1]) { bestv[ii + 1] = dd1; besti[ii + 1] = k; }
            }
        }
    }

    // cross-lane argmin over the 16 code lanes (first-index ties)
    #pragma unroll
    for (int off = 1; off < 16; off <<= 1) {
        #pragma unroll
        for (int i = 0; i < 8; ++i) {
            float ov = __shfl_xor_sync(0xffffffffu, bestv[i], off);
            int   oi = __shfl_xor_sync(0xffffffffu, besti[i], off);
            if (ov < bestv[i] || (ov == bestv[i] && oi < besti[i])) { bestv[i] = ov; besti[i] = oi; }
        }
    }
    if (tc == 0) {
        #pragma unroll
        for (int i = 0; i < 8; ++i) {
            int p = tr * 8 + i;
            idxs[p] = besti[i];
            out[OFF_IDX + n0 + p] = (float)besti[i];
            atomicAdd(&g_hist[besti[i]], 1u);
        }
    }
    __syncthreads();   // idxs visible; mainloop smem readers done

    // ---- fused quantize + straight-through + loss (xs still resident) ----
    {
        const int p = t >> 1;
        const int h = t & 1;
        const int c0 = 32 * h;
        const int k = idxs[p];
        const float* eb = emb + (size_t)k * CD + c0;
        float* ob = out + (size_t)(n0 + p) * CD + c0;
        const float* xcol = xs + c0 * XSTRIDE + p;

        double s = 0.0;
        #pragma unroll
        for (int j = 0; j < 8; ++j) {
            float4 qv = __ldg(reinterpret_cast<const float4*>(eb) + j);
            float x0 = xcol[(4 * j + 0) * XSTRIDE];
            float x1 = xcol[(4 * j + 1) * XSTRIDE];
            float x2 = xcol[(4 * j + 2) * XSTRIDE];
            float x3 = xcol[(4 * j + 3) * XSTRIDE];
            float e0 = __fsub_rn(qv.x, x0);
            float e1 = __fsub_rn(qv.y, x1);
            float e2 = __fsub_rn(qv.z, x2);
            float e3 = __fsub_rn(qv.w, x3);
            float4 o;  // straight-through: x + (q - x)
            o.x = __fadd_rn(x0, e0);
            o.y = __fadd_rn(x1, e1);
            o.z = __fadd_rn(x2, e2);
            o.w = __fadd_rn(x3, e3);
            *reinterpret_cast<float4*>(ob + 4 * j) = o;
            s += (double)__fmul_rn(e0, e0) + (double)__fmul_rn(e1, e1)
               + (double)__fmul_rn(e2, e2) + (double)__fmul_rn(e3, e3);
        }
        #pragma unroll
        for (int off = 16; off > 0; off >>= 1)
            s += __shfl_down_sync(0xffffffffu, s, off);
        if ((t & 31) == 0) red[t >> 5] = s;
        __syncthreads();
        if (t == 0) {
            double tot = 0.0;
            #pragma unroll
            for (int w = 0; w < 8; ++w) tot += red[w];
            atomicAdd(&g_loss, tot);
        }
    }
}

// ---------------- finalize ----------------
__global__ void vq_final(float* __restrict__ out) {
    __shared__ double red[256];
    int t = threadIdx.x;
    double s = 0.0;
    for (int k = t; k < KC; k += 256) {
        float cnt = (float)g_hist[k];
        float pr  = __fmul_rn(cnt, 1.0f / 65536.0f);
        float lg  = logf(__fadd_rn(pr, 1e-10f));
        s += (double)__fmul_rn(pr, lg);
    }
    red[t] = s;
    __syncthreads();
    for (int off = 128; off > 0; off >>= 1) {
        if (t < off) red[t] += red[t + off];
        __syncthreads();
    }
    if (t == 0) {
        float m = (float)(g_loss / 4194304.0);
        out[OFF_LOSS] = __fadd_rn(m, __fmul_rn(0.25f, m));
        out[OFF_PERP] = expf(-(float)red[0]);
    }
}

extern "C" void kernel_launch(void* const* d_in, const int* in_sizes, int n_in,
                              void* d_out, int out_size) {
    const float* inputs = (const float*)d_in[0];
    const float* emb    = (const float*)d_in[1];
    if (n_in >= 2 && in_sizes[0] == KC * CD && in_sizes[1] == NPTS * CD) {
        const float* tmp = inputs; inputs = emb; emb = tmp;
    }
    float* out = (float*)d_out;

    cudaFuncSetAttribute(vq_main, cudaFuncAttributeMaxDynamicSharedMemorySize, SMEM_BYTES);

    // launch order keeps vq_main at launch index 3 (ncu captures idx 3)
    vq_init_hist<<<1, 1024>>>();
    vq_esq<<<KC / 256, 256>>>(emb);
    vq_pad<<<1, 32>>>();
    vq_main<<<NPTS / MT, 256, SMEM_BYTES>>>(inputs, emb, out);
    vq_final<<<1, 256>>>(out);
}